// round 13
// baseline (speedup 1.0000x reference)
#include <cuda_runtime.h>

// DerivativeDILATEloss: soft-DTW(gamma=0.01), D[i,j]=(dy_i-dx_j)^2, B=64, n=511.
//
// Round 13: R10 machinery, but TWO independent batches per CTA (NT=512,
// 32 CTAs). Warps 0-7 = batch 2B, warps 8-15 = batch 2B+1; each SMSP hosts
// 2 warps of each batch, so one batch's chain stalls are filled by the other.
// W=2 rows/thread, direct 3-ex2 softmin in (m,s) form, free-running local
// mailboxes, predicated STS publish, dx padding, fused last-CTA reduction.

#define NSEQ   511
#define NBATCH 64
#define NT     512
#define NCTA   32
#define INFV   1.0e9f
#define PADV   1.0e4f
#define INVK   0.0069314718055994531f  // ln(2)/100
#define SQRTK  12.011224298677374f     // sqrt(100/ln2)

// dynamic smem: float2 bbuf[2][8][1024] = 128KB
#define SMEM_BYTES (2 * 8 * 1024 * 8)

__device__ __forceinline__ float ex2f(float x){float r;asm("ex2.approx.f32 %0,%1;":"=f"(r):"f"(x));return r;}
__device__ __forceinline__ float lg2f(float x){float r;asm("lg2.approx.f32 %0,%1;":"=f"(r):"f"(x));return r;}
__device__ __forceinline__ unsigned s2u(const void* p){return (unsigned)__cvta_generic_to_shared(p);}
template<int OFF>
__device__ __forceinline__ void sts_pair_pred_off(unsigned a, float m, float s, int p){
    asm volatile("{.reg .pred q; setp.ne.u32 q,%0,0; @q st.shared.v2.f32 [%1+%4],{%2,%3};}"
                 ::"r"(p),"r"(a),"f"(m),"f"(s),"n"(OFF):"memory");
}
__device__ __forceinline__ void strel_pred(unsigned a, int v, int p){
    asm volatile("{.reg .pred q; setp.ne.u32 q,%0,0; @q st.release.cta.shared.b32 [%1],%2;}"
                 ::"r"(p),"r"(a),"r"(v):"memory");
}
__device__ __forceinline__ int ld_acq(unsigned a){
    int v; asm volatile("ld.acquire.cta.shared.b32 %0,[%1];":"=r"(v):"r"(a):"memory"); return v;
}

__device__ float g_partial[NBATCH];
__device__ int   g_done = 0;

// one cell, (m,s) form (value = m - log2 s), direct 3-ex2 softmin.
#define CELL(NM, NS, AM, AS, EM, ES, CM, CS, DY, DX)                         \
    {                                                                        \
        const float mnm = fminf(fminf((AM), (EM)), (CM));                    \
        const float x1 = ex2f(mnm - (AM));                                   \
        const float x2 = ex2f(mnm - (EM));                                   \
        const float x3 = ex2f(mnm - (CM));                                   \
        NS = fmaf((AS), x1, fmaf((ES), x2, (CS) * x3));                      \
        const float dv = (DY) - (DX);                                        \
        NM = fmaf(dv, dv, mnm);                                              \
    }

__global__ __launch_bounds__(NT, 1)
void sdtw_kernel(const float* __restrict__ input,
                 const float* __restrict__ target,
                 float* __restrict__ out)
{
    __shared__ float sdxp[2][1536];    // per-group padded scaled dx (base 512)
    __shared__ int   cnt[2][16];       // per-group: [0..7] progress, [15] sentinel
    __shared__ int   slast;
    extern __shared__ float2 bbuf[];   // [2][8][1024]; row 7 = dummy per group

    const int t  = threadIdx.x;
    const int g  = t >> 8;             // batch group within CTA (0/1)
    const int tg = t & 255;            // thread index within group
    const int w  = tg >> 5;            // warp within group (0..7)
    const int lane = t & 31;
    const int b = 2 * blockIdx.x + g;  // global batch

    const float* in_b = input  + b * 512;
    const float* tg_b = target + b * 512;

    #pragma unroll
    for (int rep = 0; rep < 6; ++rep) {
        int idx = tg + rep * 256, q = idx - 512;
        float v = PADV;
        if (q >= 0 && q < NSEQ) v = (in_b[q + 1] - in_b[q]) * SQRTK;
        sdxp[g][idx] = v;
    }
    float2* gb = bbuf + g * 8 * 1024;
    #pragma unroll
    for (int rep = 0; rep < 4; ++rep)          // dummy row 7: (INF, 1)
        gb[7 * 1024 + tg + rep * 256] = make_float2(INFV, 1.0f);
    if (tg < 16) cnt[g][tg] = (tg == 15) ? 0x7FFFFFFF : 0;
    if (t == 0) slast = 0;

    const int i0 = 2 * tg;                     // rows i0, i0+1
    float dyr0, dyr1;
    dyr0 = (i0 >= 1) ? (tg_b[i0]     - tg_b[i0 - 1]) * SQRTK : 0.0f;
    dyr1 =             (tg_b[i0 + 1] - tg_b[i0])     * SQRTK;
    __syncthreads();   // only CTA-wide barrier

    // state (m,s): r1 = diag d-1, r2 = diag d-2, per owned row
    float r1m0 = INFV, r1s0 = 1.0f, r1m1 = INFV, r1s1 = 1.0f;
    float r2m0 = INFV, r2s0 = 1.0f;
    if (tg == 0) r2m0 = 0.0f;                  // R[0,0] = 0
    float tn2m = INFV, tn2s = 1.0f;            // row i0-1 @ diag d-2
    float mbm  = INFV, mbs  = 1.0f;            // lane-0 boundary @ diag d-1
    float dxw0 = sdxp[g][512 + 1 - i0];        // dx[d-i0-1] @ d=2
    float dxw1 = sdxp[g][512 - i0];            // dx[d-i0-2] @ d=2

    const float2* subrow = gb + ((w == 0) ? 7 : (w - 1)) * 1024;
    unsigned pub_a  = s2u(&gb[w * 1024]) + 2u * 8u;     // slot d0=2
    unsigned cnt_a  = s2u(&cnt[g][w]);
    unsigned cntp_a = s2u(&cnt[g][(w == 0) ? 15 : (w - 1)]);
    const int ispub = (lane == 31 && w < 7) ? 1 : 0;
    int cc = 0;
    const float* dxsrc = sdxp[g] + 512 - i0;

    #pragma unroll 1
    for (int d0 = 2; d0 <= 1018; d0 += 4) {
        const int need = d0 + 3;
        if (cc < need) { do { cc = ld_acq(cntp_a); } while (cc < need); }

        // batched boundary fetch: slots d0..d0+3 (consumed at steps d0+1..)
        const float4 bl0 = *reinterpret_cast<const float4*>(subrow + d0);
        const float4 bl1 = *reinterpret_cast<const float4*>(subrow + d0 + 2);

        #pragma unroll
        for (int u = 0; u < 4; ++u) {
            const int d = d0 + u;
            const float shm = __shfl_up_sync(0xFFFFFFFFu, r1m1, 1);
            const float shs = __shfl_up_sync(0xFFFFFFFFu, r1s1, 1);
            const float um = (lane == 0) ? mbm : shm;
            const float us = (lane == 0) ? mbs : shs;

            float nm0, ns0, nm1, ns1;
            CELL(nm0, ns0, tn2m, tn2s, um,   us,   r1m0, r1s0, dyr0, dxw0)
            CELL(nm1, ns1, r2m0, r2s0, r1m0, r1s0, r1m1, r1s1, dyr1, dxw1)

            if (u == 3) {   // exact power-of-2 renorm of s into m
                unsigned sb0 = __float_as_uint(ns0);
                int e0 = (int)(sb0 >> 23) - 127;
                ns0 = __uint_as_float((sb0 & 0x007FFFFFu) | 0x3F800000u);
                nm0 -= (float)e0;
                unsigned sb1 = __float_as_uint(ns1);
                int e1 = (int)(sb1 >> 23) - 127;
                ns1 = __uint_as_float((sb1 & 0x007FFFFFu) | 0x3F800000u);
                nm1 -= (float)e1;
            }

            if (u == 0) sts_pair_pred_off<0 >(pub_a, nm1, ns1, ispub);
            if (u == 1) sts_pair_pred_off<8 >(pub_a, nm1, ns1, ispub);
            if (u == 2) sts_pair_pred_off<16>(pub_a, nm1, ns1, ispub);
            if (u == 3) sts_pair_pred_off<24>(pub_a, nm1, ns1, ispub);
            if (u == 3) strel_pred(cnt_a, d, ispub);

            tn2m = um;  tn2s = us;
            r2m0 = r1m0; r2s0 = r1s0;
            r1m0 = nm0;  r1s0 = ns0;  r1m1 = nm1;  r1s1 = ns1;
            dxw1 = dxw0;
            dxw0 = dxsrc[d];                               // dx for step d+1
            mbm = (u == 0) ? bl0.x : (u == 1) ? bl0.z : (u == 2) ? bl1.x : bl1.z;
            mbs = (u == 0) ? bl0.y : (u == 1) ? bl0.w : (u == 2) ? bl1.y : bl1.w;
        }
        pub_a += 32u;
    }

    // tail step d = 1022 (no publish/poll)
    float resm, ress;
    {
        const float shm = __shfl_up_sync(0xFFFFFFFFu, r1m1, 1);
        const float shs = __shfl_up_sync(0xFFFFFFFFu, r1s1, 1);
        const float um = (lane == 0) ? mbm : shm;
        const float us = (lane == 0) ? mbs : shs;
        float nm1, ns1;
        CELL(nm1, ns1, r2m0, r2s0, r1m0, r1s0, r1m1, r1s1, dyr1, dxw1)
        (void)um; (void)us;
        resm = nm1; ress = ns1;
    }

    // fused reduction: each group's row 511 writes partial; last CTA reduces
    if (tg == 255) {
        g_partial[b] = (resm - lg2f(ress)) * INVK;
        __threadfence();
    }
    __syncthreads();
    if (t == 0) {
        int prev = atomicAdd(&g_done, 1);
        slast = (prev == NCTA - 1) ? 1 : 0;
    }
    __syncthreads();
    if (slast && t < 32) {
        __threadfence();
        float s = g_partial[t] + g_partial[t + 32];
        #pragma unroll
        for (int o = 16; o > 0; o >>= 1)
            s += __shfl_down_sync(0xFFFFFFFFu, s, o);
        if (t == 0) { out[0] = s * (1.0f / (float)NBATCH); g_done = 0; }
    }
}

extern "C" void kernel_launch(void* const* d_in, const int* in_sizes, int n_in,
                              void* d_out, int out_size)
{
    const float* input  = (const float*)d_in[0];
    const float* target = (const float*)d_in[1];
    float* out = (float*)d_out;

    cudaFuncSetAttribute(sdtw_kernel,
                         cudaFuncAttributeMaxDynamicSharedMemorySize, SMEM_BYTES);
    sdtw_kernel<<<NCTA, NT, SMEM_BYTES>>>(input, target, out);
}

// round 14
// speedup vs baseline: 1.3113x; 1.3113x over previous
#include <cuda_runtime.h>

// DerivativeDILATEloss: soft-DTW(gamma=0.01), D[i,j]=(dy_i-dx_j)^2, B=64, n=511.
//
// Round 14: W=1 row/thread, NT=512 (16 warps -> 4 warps/SMSP of the SAME
// batch, mutually skewed via free-running mailboxes => high issue efficiency,
// all 64 CTAs). R10 machinery: (m,s) form (no lg2 in loop), direct 3-ex2
// softmin, batched LDS.128 boundary fetch + amortized poll per 4-step block,
// predicated immediate-offset STS publish, dx padding. Fused reduction.

#define NSEQ   511
#define NBATCH 64
#define NT     512
#define INFV   1.0e9f
#define PADV   1.0e4f
#define INVK   0.0069314718055994531f  // ln(2)/100
#define SQRTK  12.011224298677374f     // sqrt(100/ln2)

// dynamic smem: float2 bbuf[16][1024] = 128KB (rows 0..14 producers, 15 dummy)
#define SMEM_BYTES (16 * 1024 * 8)

__device__ __forceinline__ float ex2f(float x){float r;asm("ex2.approx.f32 %0,%1;":"=f"(r):"f"(x));return r;}
__device__ __forceinline__ float lg2f(float x){float r;asm("lg2.approx.f32 %0,%1;":"=f"(r):"f"(x));return r;}
__device__ __forceinline__ unsigned s2u(const void* p){return (unsigned)__cvta_generic_to_shared(p);}
template<int OFF>
__device__ __forceinline__ void sts_pair_pred_off(unsigned a, float m, float s, int p){
    asm volatile("{.reg .pred q; setp.ne.u32 q,%0,0; @q st.shared.v2.f32 [%1+%4],{%2,%3};}"
                 ::"r"(p),"r"(a),"f"(m),"f"(s),"n"(OFF):"memory");
}
__device__ __forceinline__ void strel_pred(unsigned a, int v, int p){
    asm volatile("{.reg .pred q; setp.ne.u32 q,%0,0; @q st.release.cta.shared.b32 [%1],%2;}"
                 ::"r"(p),"r"(a),"r"(v):"memory");
}
__device__ __forceinline__ int ld_acq(unsigned a){
    int v; asm volatile("ld.acquire.cta.shared.b32 %0,[%1];":"=r"(v):"r"(a):"memory"); return v;
}

__device__ float g_partial[NBATCH];
__device__ int   g_done = 0;

__global__ __launch_bounds__(NT, 1)
void sdtw_kernel(const float* __restrict__ input,
                 const float* __restrict__ target,
                 float* __restrict__ out)
{
    __shared__ float sdxp[1536];   // padded scaled dx, logical base 512
    __shared__ int   cnt[16];      // [0..14] producer progress, [15] sentinel
    __shared__ int   slast;
    extern __shared__ float2 bbuf[];   // [16][1024]

    const int b = blockIdx.x, t = threadIdx.x, w = t >> 5, lane = t & 31;
    const float* in_b = input  + b * 512;
    const float* tg_b = target + b * 512;

    #pragma unroll
    for (int rep = 0; rep < 3; ++rep) {
        int idx = t + rep * NT, q = idx - 512;
        float v = PADV;
        if (q >= 0 && q < NSEQ) v = (in_b[q + 1] - in_b[q]) * SQRTK;
        sdxp[idx] = v;
    }
    #pragma unroll
    for (int rep = 0; rep < 2; ++rep)          // dummy row 15: (INF, 1)
        bbuf[15 * 1024 + t + rep * NT] = make_float2(INFV, 1.0f);
    if (t < 16) cnt[t] = (t == 15) ? 0x7FFFFFFF : 0;
    if (t == 0) slast = 0;

    const int i = t;                           // owned row
    const float dyr = (i >= 1) ? (tg_b[i] - tg_b[i - 1]) * SQRTK : 0.0f;
    __syncthreads();   // only CTA-wide barrier

    // state (m,s): value = m - log2(s)
    float r1m = INFV, r1s = 1.0f;              // own row @ diag d-1
    float am  = (i == 1) ? 0.0f : INFV;        // row i-1 @ diag d-2 (R[0,0] seed)
    float as_ = 1.0f;
    float mbm = INFV, mbs = 1.0f;              // lane-0 boundary @ diag d-1
    const float* dxp = sdxp + 512 - i - 1;     // dxp[d] = scaled dx[j-1]
    float dxv = dxp[2];

    const float2* subrow = bbuf + ((w == 0) ? 15 : (w - 1)) * 1024;
    unsigned pub_a  = s2u(&bbuf[((w < 15) ? w : 0) * 1024]) + 2u * 8u;  // slot d0=2
    unsigned cnt_a  = s2u(&cnt[w]);
    unsigned cntp_a = s2u(&cnt[(w == 0) ? 15 : (w - 1)]);
    const int ispub = (lane == 31 && w < 15) ? 1 : 0;
    int cc = 0;

    #pragma unroll 1
    for (int d0 = 2; d0 <= 1018; d0 += 4) {
        const int need = d0 + 3;
        if (cc < need) { do { cc = ld_acq(cntp_a); } while (cc < need); }

        // batched boundary fetch: slots d0..d0+3 (consumed at steps d0+1..)
        const float4 bl0 = *reinterpret_cast<const float4*>(subrow + d0);
        const float4 bl1 = *reinterpret_cast<const float4*>(subrow + d0 + 2);

        #pragma unroll
        for (int u = 0; u < 4; ++u) {
            const int d = d0 + u;
            const float shm = __shfl_up_sync(0xFFFFFFFFu, r1m, 1);
            const float shs = __shfl_up_sync(0xFFFFFFFFu, r1s, 1);
            const float um = (lane == 0) ? mbm : shm;
            const float us = (lane == 0) ? mbs : shs;

            const float mnm = fminf(fminf(am, um), r1m);
            const float x1 = ex2f(mnm - am);
            const float x2 = ex2f(mnm - um);
            const float x3 = ex2f(mnm - r1m);
            float ns = fmaf(as_, x1, fmaf(us, x2, r1s * x3));
            const float dv = dyr - dxv;
            float nm = fmaf(dv, dv, mnm);

            if (u == 3) {   // exact power-of-2 renorm of s into m
                unsigned sb = __float_as_uint(ns);
                int e = (int)(sb >> 23) - 127;
                ns = __uint_as_float((sb & 0x007FFFFFu) | 0x3F800000u);
                nm -= (float)e;
            }

            if (u == 0) sts_pair_pred_off<0 >(pub_a, nm, ns, ispub);
            if (u == 1) sts_pair_pred_off<8 >(pub_a, nm, ns, ispub);
            if (u == 2) sts_pair_pred_off<16>(pub_a, nm, ns, ispub);
            if (u == 3) sts_pair_pred_off<24>(pub_a, nm, ns, ispub);
            if (u == 3) strel_pred(cnt_a, d, ispub);

            am = um; as_ = us;
            r1m = nm; r1s = ns;
            dxv = dxp[d + 1];
            mbm = (u == 0) ? bl0.x : (u == 1) ? bl0.z : (u == 2) ? bl1.x : bl1.z;
            mbs = (u == 0) ? bl0.y : (u == 1) ? bl0.w : (u == 2) ? bl1.y : bl1.w;
        }
        pub_a += 32u;
    }

    // tail step d = 1022 (no publish/poll)
    float resm, ress;
    {
        const float shm = __shfl_up_sync(0xFFFFFFFFu, r1m, 1);
        const float shs = __shfl_up_sync(0xFFFFFFFFu, r1s, 1);
        const float um = (lane == 0) ? mbm : shm;
        const float us = (lane == 0) ? mbs : shs;
        const float mnm = fminf(fminf(am, um), r1m);
        const float x1 = ex2f(mnm - am);
        const float x2 = ex2f(mnm - um);
        const float x3 = ex2f(mnm - r1m);
        ress = fmaf(as_, x1, fmaf(us, x2, r1s * x3));
        const float dv = dyr - dxv;
        resm = fmaf(dv, dv, mnm);
    }

    // fused reduction: last CTA sums g_partial and writes out
    if (t == NT - 1) {                          // row 511
        g_partial[b] = (resm - lg2f(ress)) * INVK;
        __threadfence();
        int prev = atomicAdd(&g_done, 1);
        slast = (prev == NBATCH - 1) ? 1 : 0;
    }
    __syncthreads();
    if (slast && t < 32) {
        __threadfence();
        float s = g_partial[t] + g_partial[t + 32];
        #pragma unroll
        for (int o = 16; o > 0; o >>= 1)
            s += __shfl_down_sync(0xFFFFFFFFu, s, o);
        if (t == 0) { out[0] = s * (1.0f / (float)NBATCH); g_done = 0; }
    }
}

extern "C" void kernel_launch(void* const* d_in, const int* in_sizes, int n_in,
                              void* d_out, int out_size)
{
    const float* input  = (const float*)d_in[0];
    const float* target = (const float*)d_in[1];
    float* out = (float*)d_out;

    cudaFuncSetAttribute(sdtw_kernel,
                         cudaFuncAttributeMaxDynamicSharedMemorySize, SMEM_BYTES);
    sdtw_kernel<<<NBATCH, NT, SMEM_BYTES>>>(input, target, out);
}